// round 13
// baseline (speedup 1.0000x reference)
#include <cuda_runtime.h>
#include <cuda_fp16.h>
#include <stdint.h>

#define NHEADS 16
#define DMODEL 2048
#define DHEAD  128
#define ROTD   64
#define BATCHN 4
#define SEQL   2048
#define MTOT   (BATCHN*SEQL)     /* 8192 */
#define KTOT   DMODEL            /* 2048 */
#define NSEG   (NHEADS*DHEAD)    /* 2048 */
#define NTOT   (3*NSEG)          /* 6144 */

#define BM 128
#define BN 128
#define BK 64
#define KITERS (KTOT/BK)         /* 32 */
#define STAGES 3
#define THREADS 256
#define STAGE_A (BM*BK*2)        /* 16384 */
#define STAGE_B (BN*BK*2)

#define RES_F4  ((MTOT*DMODEL)/4)            /* 4194304 float4 */
#define GRID_X  (NTOT/BN)                    /* 48 */
#define GRID_Y  (MTOT/BM)                    /* 64 */
#define RSTRIDE (GRID_X*GRID_Y*THREADS)      /* 786432 */

// ---- scratch (device globals: no allocation allowed) ----
__device__ __half g_Xh[(size_t)MTOT * KTOT];   // x in fp16, row-major [M][K]
__device__ __half g_Wh[(size_t)NTOT * KTOT];   // packed B^T in fp16, [N][K]
__device__ float2 g_rope[SEQL * (ROTD / 2)];   // (cos, sin) per (pos, pair)

// ------------------------------------------------------------------
// Prologue kernels
// ------------------------------------------------------------------
__global__ void convert_x_kernel(const float4* __restrict__ x, int n4) {
    int i = blockIdx.x * blockDim.x + threadIdx.x;
    if (i < n4) {
        float4 v = x[i];
        __half2 h0 = __floats2half2_rn(v.x, v.y);
        __half2 h1 = __floats2half2_rn(v.z, v.w);
        uint2 u;
        u.x = *reinterpret_cast<uint32_t*>(&h0);
        u.y = *reinterpret_cast<uint32_t*>(&h1);
        reinterpret_cast<uint2*>(g_Xh)[i] = u;
    }
}

__global__ void pack_w_kernel(const float* __restrict__ Wq,
                              const float* __restrict__ Wk,
                              const float* __restrict__ Wv) {
    __shared__ float t[32][33];
    int h   = blockIdx.z & 15;
    int seg = blockIdx.z >> 4;
    const float* W = (seg == 0) ? Wq : (seg == 1) ? Wk : Wv;
    const float* base = W + (size_t)h * DMODEL * DHEAD;
    int d0 = blockIdx.x * 32;
    int e0 = blockIdx.y * 32;
    int tx = threadIdx.x, ty = threadIdx.y;
#pragma unroll
    for (int i = 0; i < 4; i++) {
        int dl = ty + i * 8;
        t[dl][tx] = base[(size_t)(d0 + dl) * DHEAD + e0 + tx];
    }
    __syncthreads();
#pragma unroll
    for (int i = 0; i < 4; i++) {
        int el = ty + i * 8;
        int n  = seg * NSEG + h * DHEAD + e0 + el;
        g_Wh[(size_t)n * KTOT + d0 + tx] = __float2half_rn(t[tx][el]);
    }
}

__global__ void rope_table_kernel() {
    int i = blockIdx.x * blockDim.x + threadIdx.x;
    if (i < SEQL * (ROTD / 2)) {
        int pos = i >> 5;        // ROTD/2 == 32
        int j   = i & 31;
        double freq = exp(log(10000.0) * (double)j / 32.0);
        double a = (double)pos / freq;
        g_rope[i] = make_float2((float)cos(a), (float)sin(a));
    }
}

// ------------------------------------------------------------------
// Main fused GEMM + bias + rotary + residual copy
// ------------------------------------------------------------------
__device__ __forceinline__ uint32_t smem_u32(const void* p) {
    uint32_t a;
    asm("{.reg .u64 t; cvta.to.shared.u64 t, %1; cvt.u32.u64 %0, t;}"
        : "=r"(a) : "l"(p));
    return a;
}

#define LDMX4(addr, r0, r1, r2, r3) \
    asm volatile("ldmatrix.sync.aligned.m8n8.x4.shared.b16 {%0,%1,%2,%3}, [%4];" \
                 : "=r"(r0), "=r"(r1), "=r"(r2), "=r"(r3) : "r"(addr))

extern "C" __global__ void __launch_bounds__(THREADS, 2)
qkv_gemm_kernel(const float* __restrict__ residual,
                const float* __restrict__ bQ, const float* __restrict__ bK,
                const float* __restrict__ bV, float* __restrict__ out) {
    extern __shared__ __half smem[];
    const uint32_t As_u = smem_u32(smem);
    const uint32_t Bs_u = As_u + STAGES * STAGE_A;

    const int tid  = threadIdx.x;
    const int lane = tid & 31;
    const int warp = tid >> 5;
    const int wm = warp & 1;   // 0..1 -> m offset *64
    const int wn = warp >> 1;  // 0..3 -> n offset *32

    const int m0 = blockIdx.y * BM;
    const int n0 = blockIdx.x * BN;
    const int seg = n0 / NSEG;          // 0=q 1=k 2=v (block uniform)
    const int w0  = n0 - seg * NSEG;    // column within segment (mult of 128)

    // per-warp ks phase: warps w and w+4 share an SMSP -> offset them by 2 ks
    const int phase = (warp >> 2) * 2;

    // hoisted ldmatrix base addresses: swizzle bits 4-6 applied by XOR at use
    const uint32_t lx7 = (lane & 7) << 4;
    const uint32_t kx0 = (lane >> 4);   // column-half selector
    uint32_t baseA[STAGES][4], baseB[STAGES][2];
#pragma unroll
    for (int s = 0; s < STAGES; s++) {
#pragma unroll
        for (int mt = 0; mt < 4; mt++)
            baseA[s][mt] = As_u + s * STAGE_A +
                           (wm * 64 + mt * 16 + (lane & 15)) * 128 + lx7;
#pragma unroll
        for (int bt = 0; bt < 2; bt++)
            baseB[s][bt] = Bs_u + s * STAGE_B +
                           (wn * 32 + bt * 16 + (lane & 15)) * 128 + lx7;
    }

    // hoisted cp.async source/dest bases (constant across kt)
    const int crow = tid >> 3;           // 0..31 (+32 per i)
    const int cc   = tid & 7;
    const int cch  = cc ^ (crow & 7);    // swizzle (row&7 invariant under +32)
    const __half* pA0 = &g_Xh[(size_t)(m0 + crow) * KTOT + cc * 8];
    const __half* pB0 = &g_Wh[(size_t)(n0 + crow) * KTOT + cc * 8];
    const uint32_t dof = crow * 128 + (cch << 4);

    auto load_stage = [&](int stg, int k0) {
        uint32_t ad = As_u + stg * STAGE_A + dof;
        uint32_t bd = Bs_u + stg * STAGE_B + dof;
        const __half* pa = pA0 + k0;
        const __half* pb = pB0 + k0;
#pragma unroll
        for (int i = 0; i < 4; i++) {
            asm volatile("cp.async.cg.shared.global [%0], [%1], 16;\n"
                         :: "r"(ad + i * (32 * 128)),
                            "l"(pa + (size_t)i * 32 * KTOT) : "memory");
            asm volatile("cp.async.cg.shared.global [%0], [%1], 16;\n"
                         :: "r"(bd + i * (32 * 128)),
                            "l"(pb + (size_t)i * 32 * KTOT) : "memory");
        }
    };

    float acc[4][4][4];
#pragma unroll
    for (int i = 0; i < 4; i++)
#pragma unroll
        for (int j = 0; j < 4; j++)
#pragma unroll
            for (int k = 0; k < 4; k++) acc[i][j][k] = 0.f;

    load_stage(0, 0);
    asm volatile("cp.async.commit_group;\n" ::: "memory");
    load_stage(1, BK);
    asm volatile("cp.async.commit_group;\n" ::: "memory");

    // ---- residual passthrough, hidden in the GEMM's memory slack ----
    {
        const float4* rsrc = reinterpret_cast<const float4*>(residual);
        float4* rdst = reinterpret_cast<float4*>(out);
        int rid = (blockIdx.y * GRID_X + blockIdx.x) * THREADS + tid;
#pragma unroll
        for (int j = 0; j < 6; j++) {
            int idx = rid + j * RSTRIDE;
            if (idx < RES_F4) rdst[idx] = rsrc[idx];
        }
    }

// one kt iteration; S is a literal stage index (compile-time)
#define KT_BODY(S, KT_)                                                        \
    do {                                                                       \
        const int kt_ = (KT_);                                                 \
        asm volatile("cp.async.wait_group 1;\n" ::: "memory");                 \
        __syncthreads();                                                       \
        if (kt_ + 2 < KITERS) load_stage((S + 2) % 3, (kt_ + 2) * BK);         \
        asm volatile("cp.async.commit_group;\n" ::: "memory");                 \
        _Pragma("unroll")                                                      \
        for (int ksi = 0; ksi < 4; ksi++) {                                    \
            int ks  = (ksi + phase) & 3;                                       \
            uint32_t chA = (ks * 2 + kx0) << 4;                                \
            uint32_t fa[4][4], fb[4][2];                                       \
            _Pragma("unroll")                                                  \
            for (int mt = 0; mt < 4; mt++)                                     \
                LDMX4(baseA[S][mt] ^ chA,                                      \
                      fa[mt][0], fa[mt][1], fa[mt][2], fa[mt][3]);             \
            _Pragma("unroll")                                                  \
            for (int bt = 0; bt < 2; bt++) {                                   \
                uint32_t r0, r1, r2, r3;                                       \
                LDMX4(baseB[S][bt] ^ chA, r0, r1, r2, r3);                     \
                fb[bt * 2][0] = r0;     fb[bt * 2][1] = r2;                    \
                fb[bt * 2 + 1][0] = r1; fb[bt * 2 + 1][1] = r3;                \
            }                                                                  \
            _Pragma("unroll")                                                  \
            for (int mt = 0; mt < 4; mt++)                                     \
                _Pragma("unroll")                                              \
                for (int nt = 0; nt < 4; nt++)                                 \
                    asm volatile(                                              \
                        "mma.sync.aligned.m16n8k16.row.col.f32.f16.f16.f32 "   \
                        "{%0,%1,%2,%3}, {%4,%5,%6,%7}, {%8,%9}, {%0,%1,%2,%3};"\
                        : "+f"(acc[mt][nt][0]), "+f"(acc[mt][nt][1]),          \
                          "+f"(acc[mt][nt][2]), "+f"(acc[mt][nt][3])           \
                        : "r"(fa[mt][0]), "r"(fa[mt][1]),                      \
                          "r"(fa[mt][2]), "r"(fa[mt][3]),                      \
                          "r"(fb[nt][0]), "r"(fb[nt][1]));                     \
        }                                                                      \
    } while (0)

    for (int ktb = 0; ktb < 30; ktb += 3) {
        KT_BODY(0, ktb);
        KT_BODY(1, ktb + 1);
        KT_BODY(2, ktb + 2);
    }
    KT_BODY(0, 30);
    KT_BODY(1, 31);
#undef KT_BODY

    // -------- epilogue: bias + rotary, direct float2 stores ----
    const float* bias = (seg == 0) ? bQ : (seg == 1) ? bK : bV;
    const int cp = (lane & 3) << 1;              // column pair in nt block
    const bool dorope = (seg < 2) && (wn < 2);   // warp-uniform: cols 0..63

    float2 bv[4];
#pragma unroll
    for (int nt = 0; nt < 4; nt++)
        bv[nt] = *reinterpret_cast<const float2*>(&bias[w0 + wn * 32 + nt * 8 + cp]);

    size_t obase = (size_t)(1 + seg) * ((size_t)MTOT * NSEG);
#pragma unroll
    for (int mt = 0; mt < 4; mt++) {
#pragma unroll
        for (int hh = 0; hh < 2; hh++) {
            int rl  = wm * 64 + mt * 16 + (lane >> 2) + hh * 8;
            int pos = (m0 + rl) & (SEQL - 1);
            float* orow = &out[obase + (size_t)(m0 + rl) * NSEG + w0 + wn * 32];
            const float2* rrow = &g_rope[pos * (ROTD / 2) + wn * 16];
#pragma unroll
            for (int nt = 0; nt < 4; nt++) {
                int c = nt * 8 + cp;             // 0..31 within warp block
                float v0 = acc[mt][nt][hh * 2 + 0] + bv[nt].x;
                float v1 = acc[mt][nt][hh * 2 + 1] + bv[nt].y;
                if (dorope) {
                    float2 cs = rrow[c >> 1];
                    float t0 = v0 * cs.x - v1 * cs.y;
                    v1 = v1 * cs.x + v0 * cs.y;
                    v0 = t0;
                }
                *reinterpret_cast<float2*>(&orow[c]) = make_float2(v0, v1);
            }
        }
    }
}

// ------------------------------------------------------------------
// Launch
// ------------------------------------------------------------------
extern "C" void kernel_launch(void* const* d_in, const int* in_sizes, int n_in,
                              void* d_out, int out_size) {
    const float* residual = (const float*)d_in[0];
    const float* x  = (const float*)d_in[1];
    const float* Wq = (const float*)d_in[2];
    const float* Wk = (const float*)d_in[3];
    const float* Wv = (const float*)d_in[4];
    const float* bQ = (const float*)d_in[5];
    const float* bK = (const float*)d_in[6];
    const float* bV = (const float*)d_in[7];
    float* out = (float*)d_out;

    cudaFuncSetAttribute(qkv_gemm_kernel,
                         cudaFuncAttributeMaxDynamicSharedMemorySize,
                         STAGES * (STAGE_A + STAGE_B));

    // prologues
    int n4 = (MTOT * KTOT) / 4;
    convert_x_kernel<<<(n4 + 255) / 256, 256>>>(
        reinterpret_cast<const float4*>(x), n4);
    dim3 pw_grid(DMODEL / 32, DHEAD / 32, 48);
    pack_w_kernel<<<pw_grid, dim3(32, 8)>>>(Wq, Wk, Wv);
    rope_table_kernel<<<(SEQL * (ROTD / 2) + 255) / 256, 256>>>();

    // fused GEMM + bias + rotary + residual copy
    dim3 grid(GRID_X, GRID_Y);
    qkv_gemm_kernel<<<grid, THREADS, STAGES * (STAGE_A + STAGE_B)>>>(
        residual, bQ, bK, bV, out);
}

// round 16
// speedup vs baseline: 1.1689x; 1.1689x over previous
#include <cuda_runtime.h>
#include <cuda_fp16.h>
#include <stdint.h>

#define NHEADS 16
#define DMODEL 2048
#define DHEAD  128
#define ROTD   64
#define BATCHN 4
#define SEQL   2048
#define MTOT   (BATCHN*SEQL)     /* 8192 */
#define KTOT   DMODEL            /* 2048 */
#define NSEG   (NHEADS*DHEAD)    /* 2048 */
#define NTOT   (3*NSEG)          /* 6144 */

#define BM 128
#define BN 128
#define BK 64
#define KITERS (KTOT/BK)         /* 32 */
#define STAGES 3
#define THREADS 256
#define STAGE_A (BM*BK*2)        /* 16384 */
#define STAGE_B (BN*BK*2)
#define SMEM_REQ (1024 + STAGES*(STAGE_A+STAGE_B))

#define RES_F4  ((MTOT*DMODEL)/4)            /* 4194304 float4 */
#define GRID_X  (NTOT/BN)                    /* 48 */
#define GRID_Y  (MTOT/BM)                    /* 64 */
#define RSTRIDE (GRID_X*GRID_Y*THREADS)      /* 786432 */

// ---- scratch (device globals: no allocation allowed) ----
__device__ __half g_Xh[(size_t)MTOT * KTOT];   // x in fp16, row-major [M][K]
__device__ __half g_Wh[(size_t)NTOT * KTOT];   // packed B^T in fp16, [N][K]
__device__ float2 g_rope[SEQL * (ROTD / 2)];   // (cos, sin) per (pos, pair)

// ------------------------------------------------------------------
// Prologue kernels
// ------------------------------------------------------------------
__global__ void convert_x_kernel(const float4* __restrict__ x, int n4) {
    int i = blockIdx.x * blockDim.x + threadIdx.x;
    if (i < n4) {
        float4 v = x[i];
        __half2 h0 = __floats2half2_rn(v.x, v.y);
        __half2 h1 = __floats2half2_rn(v.z, v.w);
        uint2 u;
        u.x = *reinterpret_cast<uint32_t*>(&h0);
        u.y = *reinterpret_cast<uint32_t*>(&h1);
        reinterpret_cast<uint2*>(g_Xh)[i] = u;
    }
}

__global__ void pack_w_kernel(const float* __restrict__ Wq,
                              const float* __restrict__ Wk,
                              const float* __restrict__ Wv) {
    __shared__ float t[32][33];
    int h   = blockIdx.z & 15;
    int seg = blockIdx.z >> 4;
    const float* W = (seg == 0) ? Wq : (seg == 1) ? Wk : Wv;
    const float* base = W + (size_t)h * DMODEL * DHEAD;
    int d0 = blockIdx.x * 32;
    int e0 = blockIdx.y * 32;
    int tx = threadIdx.x, ty = threadIdx.y;
#pragma unroll
    for (int i = 0; i < 4; i++) {
        int dl = ty + i * 8;
        t[dl][tx] = base[(size_t)(d0 + dl) * DHEAD + e0 + tx];
    }
    __syncthreads();
#pragma unroll
    for (int i = 0; i < 4; i++) {
        int el = ty + i * 8;
        int n  = seg * NSEG + h * DHEAD + e0 + el;
        g_Wh[(size_t)n * KTOT + d0 + tx] = __float2half_rn(t[tx][el]);
    }
}

__global__ void rope_table_kernel() {
    int i = blockIdx.x * blockDim.x + threadIdx.x;
    if (i < SEQL * (ROTD / 2)) {
        int pos = i >> 5;        // ROTD/2 == 32
        int j   = i & 31;
        double freq = exp(log(10000.0) * (double)j / 32.0);
        double a = (double)pos / freq;
        g_rope[i] = make_float2((float)cos(a), (float)sin(a));
    }
}

// ------------------------------------------------------------------
// PTX helpers
// ------------------------------------------------------------------
__device__ __forceinline__ uint32_t smem_u32(const void* p) {
    uint32_t a;
    asm("{.reg .u64 t; cvta.to.shared.u64 t, %1; cvt.u32.u64 %0, t;}"
        : "=r"(a) : "l"(p));
    return a;
}

#define LDMX4(addr, r0, r1, r2, r3) \
    asm volatile("ldmatrix.sync.aligned.m8n8.x4.shared.b16 {%0,%1,%2,%3}, [%4];" \
                 : "=r"(r0), "=r"(r1), "=r"(r2), "=r"(r3) : "r"(addr))

#define MBARRIER_INIT(addr, cnt) \
    asm volatile("mbarrier.init.shared.b64 [%0], %1;" \
                 :: "r"(addr), "r"(cnt) : "memory")

#define MBAR_WAIT(addr, ph) do {                                              \
    asm volatile(                                                             \
        "{\n\t.reg .pred P;\n\t"                                              \
        "WL_%=:\n\t"                                                          \
        "mbarrier.try_wait.parity.acquire.cta.shared::cta.b64 P, [%0], %1, 0x989680;\n\t" \
        "@P bra.uni WD_%=;\n\t"                                               \
        "bra.uni WL_%=;\n\t"                                                  \
        "WD_%=:\n\t}"                                                         \
        :: "r"(addr), "r"(ph) : "memory");                                    \
} while (0)

#define MBAR_ARRIVE(addr) \
    asm volatile("mbarrier.arrive.shared.b64 _, [%0];" :: "r"(addr) : "memory")

#define CPASYNC_ARRIVE(addr) \
    asm volatile("cp.async.mbarrier.arrive.noinc.shared.b64 [%0];" \
                 :: "r"(addr) : "memory")

// ------------------------------------------------------------------
// Main fused GEMM + bias + rotary + residual copy (mbarrier pipeline)
// ------------------------------------------------------------------
extern "C" __global__ void __launch_bounds__(THREADS, 2)
qkv_gemm_kernel(const float* __restrict__ residual,
                const float* __restrict__ bQ, const float* __restrict__ bK,
                const float* __restrict__ bV, float* __restrict__ out) {
    extern __shared__ __half smem[];
    const uint32_t sbase = smem_u32(smem);
    const uint32_t FULLB  = sbase;        // 3 x 8B
    const uint32_t EMPTYB = sbase + 24;   // 3 x 8B
    const uint32_t As_u = sbase + 1024;   // 1024-aligned (dyn smem is aligned)
    const uint32_t Bs_u = As_u + STAGES * STAGE_A;

    const int tid  = threadIdx.x;
    const int lane = tid & 31;
    const int warp = tid >> 5;
    const int wm = warp & 1;   // 0..1 -> m offset *64
    const int wn = warp >> 1;  // 0..3 -> n offset *32

    const int m0 = blockIdx.y * BM;
    const int n0 = blockIdx.x * BN;
    const int seg = n0 / NSEG;          // 0=q 1=k 2=v (block uniform)
    const int w0  = n0 - seg * NSEG;    // column within segment (mult of 128)

    if (tid == 0) {
#pragma unroll
        for (int s = 0; s < STAGES; s++) {
            MBARRIER_INIT(FULLB + 8 * s, THREADS);
            MBARRIER_INIT(EMPTYB + 8 * s, THREADS);
        }
    }
    __syncthreads();

    // hoisted cp.async source/dest bases (constant across kt)
    const int crow = tid >> 3;           // 0..31 (+32 per i)
    const int cc   = tid & 7;
    const int cch  = cc ^ (crow & 7);    // swizzle (row&7 invariant under +32)
    const __half* pA0 = &g_Xh[(size_t)(m0 + crow) * KTOT + cc * 8];
    const __half* pB0 = &g_Wh[(size_t)(n0 + crow) * KTOT + cc * 8];
    const uint32_t dof = crow * 128 + (cch << 4);

    auto load_stage = [&](int stg, int k0) {
        uint32_t ad = As_u + stg * STAGE_A + dof;
        uint32_t bd = Bs_u + stg * STAGE_B + dof;
        const __half* pa = pA0 + k0;
        const __half* pb = pB0 + k0;
#pragma unroll
        for (int i = 0; i < 4; i++) {
            asm volatile("cp.async.cg.shared.global [%0], [%1], 16;\n"
                         :: "r"(ad + i * (32 * 128)),
                            "l"(pa + (size_t)i * 32 * KTOT) : "memory");
            asm volatile("cp.async.cg.shared.global [%0], [%1], 16;\n"
                         :: "r"(bd + i * (32 * 128)),
                            "l"(pb + (size_t)i * 32 * KTOT) : "memory");
        }
    };

    float acc[4][4][4];
#pragma unroll
    for (int i = 0; i < 4; i++)
#pragma unroll
        for (int j = 0; j < 4; j++)
#pragma unroll
            for (int k = 0; k < 4; k++) acc[i][j][k] = 0.f;

    // prologue: fill stages 0 and 1
    load_stage(0, 0);
    CPASYNC_ARRIVE(FULLB + 0);
    load_stage(1, BK);
    CPASYNC_ARRIVE(FULLB + 8);

    // ---- residual passthrough, hidden in the GEMM's memory slack ----
    {
        const float4* rsrc = reinterpret_cast<const float4*>(residual);
        float4* rdst = reinterpret_cast<float4*>(out);
        int rid = (blockIdx.y * GRID_X + blockIdx.x) * THREADS + tid;
#pragma unroll
        for (int j = 0; j < 6; j++) {
            int idx = rid + j * RSTRIDE;
            if (idx < RES_F4) rdst[idx] = rsrc[idx];
        }
    }

    // pipeline state: consumer stage s / occupancy n; producer block kb
    int s = 0, n = 0;           // consumes block kt in stage s, parity n&1
    int sb = 2, nb = 0;         // next block kb goes to stage sb, occupancy nb

    for (int kt = 0; kt < KITERS; kt++) {
        // data ready for stage s?
        MBAR_WAIT(FULLB + 8 * s, n & 1);

        // prefetch block kt+2 into stage sb
        int kb = kt + 2;
        if (kb < KITERS) {
            if (nb >= 1) MBAR_WAIT(EMPTYB + 8 * sb, (nb - 1) & 1);
            load_stage(sb, kb * BK);
            CPASYNC_ARRIVE(FULLB + 8 * sb);
        }

        uint32_t a_st = As_u + s * STAGE_A;
        uint32_t b_st = Bs_u + s * STAGE_B;
#pragma unroll
        for (int ks = 0; ks < 4; ks++) {
            uint32_t fa[4][4], fb[4][2];
#pragma unroll
            for (int mt = 0; mt < 4; mt++) {
                int r  = wm * 64 + mt * 16 + (lane & 15);
                int ch = (ks * 2 + (lane >> 4)) ^ (r & 7);
                LDMX4(a_st + r * 128 + (ch << 4),
                      fa[mt][0], fa[mt][1], fa[mt][2], fa[mt][3]);
            }
#pragma unroll
            for (int bt = 0; bt < 2; bt++) {
                int nn = wn * 32 + bt * 16 + (lane & 15);
                int ch = (ks * 2 + (lane >> 4)) ^ (nn & 7);
                uint32_t r0, r1, r2, r3;
                LDMX4(b_st + nn * 128 + (ch << 4), r0, r1, r2, r3);
                fb[bt * 2][0] = r0;     fb[bt * 2][1] = r2;
                fb[bt * 2 + 1][0] = r1; fb[bt * 2 + 1][1] = r3;
            }
#pragma unroll
            for (int mt = 0; mt < 4; mt++)
#pragma unroll
                for (int nt = 0; nt < 4; nt++)
                    asm volatile(
                        "mma.sync.aligned.m16n8k16.row.col.f32.f16.f16.f32 "
                        "{%0,%1,%2,%3}, {%4,%5,%6,%7}, {%8,%9}, {%0,%1,%2,%3};"
                        : "+f"(acc[mt][nt][0]), "+f"(acc[mt][nt][1]),
                          "+f"(acc[mt][nt][2]), "+f"(acc[mt][nt][3])
                        : "r"(fa[mt][0]), "r"(fa[mt][1]),
                          "r"(fa[mt][2]), "r"(fa[mt][3]),
                          "r"(fb[nt][0]), "r"(fb[nt][1]));
        }

        // release stage s for reuse
        MBAR_ARRIVE(EMPTYB + 8 * s);

        // advance pipeline state
        if (++s == STAGES) { s = 0; n++; }
        if (kb < KITERS) { if (++sb == STAGES) { sb = 0; nb++; } }
    }

    // -------- epilogue: bias + rotary, direct float2 stores ----
    const float* bias = (seg == 0) ? bQ : (seg == 1) ? bK : bV;
    const int cp = (lane & 3) << 1;              // column pair in nt block
    const bool dorope = (seg < 2) && (wn < 2);   // warp-uniform: cols 0..63

    float2 bv[4];
#pragma unroll
    for (int nt = 0; nt < 4; nt++)
        bv[nt] = *reinterpret_cast<const float2*>(&bias[w0 + wn * 32 + nt * 8 + cp]);

    size_t obase = (size_t)(1 + seg) * ((size_t)MTOT * NSEG);
#pragma unroll
    for (int mt = 0; mt < 4; mt++) {
#pragma unroll
        for (int hh = 0; hh < 2; hh++) {
            int rl  = wm * 64 + mt * 16 + (lane >> 2) + hh * 8;
            int pos = (m0 + rl) & (SEQL - 1);
            float* orow = &out[obase + (size_t)(m0 + rl) * NSEG + w0 + wn * 32];
            const float2* rrow = &g_rope[pos * (ROTD / 2) + wn * 16];
#pragma unroll
            for (int nt = 0; nt < 4; nt++) {
                int c = nt * 8 + cp;             // 0..31 within warp block
                float v0 = acc[mt][nt][hh * 2 + 0] + bv[nt].x;
                float v1 = acc[mt][nt][hh * 2 + 1] + bv[nt].y;
                if (dorope) {
                    float2 cs = rrow[c >> 1];
                    float t0 = v0 * cs.x - v1 * cs.y;
                    v1 = v1 * cs.x + v0 * cs.y;
                    v0 = t0;
                }
                *reinterpret_cast<float2*>(&orow[c]) = make_float2(v0, v1);
            }
        }
    }
}

// ------------------------------------------------------------------
// Launch
// ------------------------------------------------------------------
extern "C" void kernel_launch(void* const* d_in, const int* in_sizes, int n_in,
                              void* d_out, int out_size) {
    const float* residual = (const float*)d_in[0];
    const float* x  = (const float*)d_in[1];
    const float* Wq = (const float*)d_in[2];
    const float* Wk = (const float*)d_in[3];
    const float* Wv = (const float*)d_in[4];
    const float* bQ = (const float*)d_in[5];
    const float* bK = (const float*)d_in[6];
    const float* bV = (const float*)d_in[7];
    float* out = (float*)d_out;

    cudaFuncSetAttribute(qkv_gemm_kernel,
                         cudaFuncAttributeMaxDynamicSharedMemorySize, SMEM_REQ);

    // prologues
    int n4 = (MTOT * KTOT) / 4;
    convert_x_kernel<<<(n4 + 255) / 256, 256>>>(
        reinterpret_cast<const float4*>(x), n4);
    dim3 pw_grid(DMODEL / 32, DHEAD / 32, 48);
    pack_w_kernel<<<pw_grid, dim3(32, 8)>>>(Wq, Wk, Wv);
    rope_table_kernel<<<(SEQL * (ROTD / 2) + 255) / 256, 256>>>();

    // fused GEMM + bias + rotary + residual copy
    dim3 grid(GRID_X, GRID_Y);
    qkv_gemm_kernel<<<grid, THREADS, SMEM_REQ>>>(residual, bQ, bK, bV, out);
}